// round 10
// baseline (speedup 1.0000x reference)
#include <cuda_runtime.h>
#include <cuda_bf16.h>

// YOLOv3 loss, sm_103a — single fused kernel, R6.
// Hot loop is now SCREENING ONLY: positive ⟺ ∃m: IoU>=0.5 ⟺ 3·inter >= areaA+area_m
// (exact, division-free). No argmax select chain, 1 LDS/iter (area recomputed
// from corners). The ~0.3% positive anchors re-run a cold argmax+loss path.

#define NUM_CLASSES 80
#define MAXB 64
#define MAXM 64
#define TPB 256

__device__ float        g_cls_sum[MAXB];   // zero-initialized at module load
__device__ float        g_reg_sum[MAXB];
__device__ float        g_npos[MAXB];
__device__ unsigned int g_done;

__device__ __forceinline__ float sigmoidf_fast(float x) {
    return 1.0f / (1.0f + __expf(-x));
}

__global__ void __launch_bounds__(TPB)
yolo_loss_fused(const float* __restrict__ pred,
                const float* __restrict__ ann,
                const float* __restrict__ anchors,
                float* __restrict__ out,
                int A, int M, int B) {
    __shared__ float4 s_corners[MAXM];               // x1,y1,x2,y2 (valid, compacted)
    __shared__ float  s_cx[MAXM], s_cy[MAXM], s_w[MAXM], s_h[MAXM], s_cl[MAXM];
    __shared__ int    s_cnt;
    __shared__ int    s_last;

    const int b   = blockIdx.y;
    const int tid = threadIdx.x;

    // ---- warp 0: load + compact valid boxes (M <= 32), order-preserving ----
    if (tid < 32) {
        bool  valid = false;
        float x = 0.f, y = 0.f, w = 0.f, h = 0.f, cl = -1.f;
        if (tid < M) {
            const float* bm = ann + ((size_t)b * M + tid) * 5;
            x = bm[0]; y = bm[1]; w = bm[2]; h = bm[3]; cl = bm[4];
            valid = (cl != -1.0f);
        }
        unsigned mask = __ballot_sync(0xffffffffu, valid);
        if (valid) {
            int slot = __popc(mask & ((1u << tid) - 1u));
            s_corners[slot] = make_float4(x, y, x + w, y + h);
            s_cx[slot] = x + 0.5f * w;
            s_cy[slot] = y + 0.5f * h;
            s_w[slot]  = w;
            s_h[slot]  = h;
            s_cl[slot] = cl;
        }
        if (tid == 0) s_cnt = __popc(mask);
    }
    __syncthreads();

    const int cnt = s_cnt;
    const int a   = blockIdx.x * TPB + tid;
    float clsc = 0.f, regc = 0.f, posc = 0.f;

    if (a < A) {
        const float4 an = __ldg((const float4*)anchors + a);
        const float ax = an.x, ay = an.y, aw = an.z, ah = an.w;
        const float ax1 = ax - 0.5f * aw, ay1 = ay - 0.5f * ah;
        const float ax2 = ax + 0.5f * aw, ay2 = ay + 0.5f * ah;
        const float areaA = aw * ah;

        // ---- HOT screening loop: any box with IoU >= 0.5 ?
        // IoU >= 0.5  ⟺  2·inter >= areaA + am − inter  ⟺  3·inter >= areaA + am
        // (exact; no division, no argmax bookkeeping, 1 LDS.128 per iter)
        bool hit = false;
        #pragma unroll 4
        for (int m = 0; m < cnt; m++) {
            const float4 c = s_corners[m];
            float iw = fmaxf(fminf(ax2, c.z) - fmaxf(ax1, c.x), 0.f);
            float ih = fmaxf(fminf(ay2, c.w) - fmaxf(ay1, c.y), 0.f);
            float inter = iw * ih;
            float am    = (c.z - c.x) * (c.w - c.y);
            hit |= (3.0f * inter >= areaA + am);
        }

        // ---- COLD path (~0.3% of anchors): argmax + losses ----
        if (hit) {
            posc = 1.f;

            // argmax via (inter, union) pairs; a/b > c/d ⟺ a·d > c·b (unions>0).
            // Init (-1,1): first box wins; strict '>' keeps first max -> jnp.argmax.
            float bI = -1.f, bU = 1.f;
            int   bi = 0;
            for (int m = 0; m < cnt; m++) {
                const float4 c = s_corners[m];
                float iw = fmaxf(fminf(ax2, c.z) - fmaxf(ax1, c.x), 0.f);
                float ih = fmaxf(fminf(ay2, c.w) - fmaxf(ay1, c.y), 0.f);
                float inter = iw * ih;
                float uni   = areaA + (c.z - c.x) * (c.w - c.y) - inter;
                if (inter * bU > bI * uni) { bI = inter; bU = uni; bi = m; }
            }

            const float* row = pred + ((size_t)b * A + a) * (NUM_CLASSES + 5);

            // regression: sum of squared errors (both /denom deferred)
            float r0 = row[0], r1 = row[1], r2 = row[2], r3 = row[3], r4 = row[4];
            float stx = sigmoidf_fast(s_cx[bi] - ax);
            float sty = sigmoidf_fast(s_cy[bi] - ay);
            float tw  = __logf(fmaxf(s_w[bi], 1.f) / aw);
            float th  = __logf(fmaxf(s_h[bi], 1.f) / ah);
            float d0 = sigmoidf_fast(r0) - stx;
            float d1 = sigmoidf_fast(r1) - sty;
            float d2 = r2 - tw;
            float d3 = r3 - th;
            float d4 = r4 - 1.0f;
            regc = d0*d0 + d1*d1 + d2*d2 + d3*d3 + d4*d4;

            // one-hot BCE collapsed: -( log p_t - log(1-p_t) + sum_c log(1-p_c) )
            float acc = 0.f;
            #pragma unroll 8
            for (int c = 0; c < NUM_CLASSES; c++)
                acc += __logf(1.0f - row[5 + c]);
            int t = (int)s_cl[bi];
            float pt = row[5 + t];
            clsc = -(__logf(pt) - __logf(1.0f - pt) + acc);
        }
    }

    // warp reduce, one conditional atomic triple per warp
    const unsigned full = 0xffffffffu;
    #pragma unroll
    for (int off = 16; off > 0; off >>= 1) {
        clsc += __shfl_down_sync(full, clsc, off);
        regc += __shfl_down_sync(full, regc, off);
        posc += __shfl_down_sync(full, posc, off);
    }
    if ((tid & 31) == 0 && posc > 0.f) {
        atomicAdd(&g_cls_sum[b], clsc);
        atomicAdd(&g_reg_sum[b], regc);
        atomicAdd(&g_npos[b],    posc);
    }

    // ---- last-block finalize ----
    __syncthreads();
    if (tid == 0) {
        __threadfence();
        unsigned total = gridDim.x * gridDim.y;
        unsigned old = atomicAdd(&g_done, 1u);
        s_last = (old == total - 1u);
    }
    __syncthreads();

    if (s_last && tid < 32) {
        __threadfence();
        float cl = 0.f, rg = 0.f;
        if (tid < B) {
            float n = g_npos[tid];
            float denom = fmaxf(n, 1.f);
            cl = g_cls_sum[tid] / denom;
            rg = (n > 0.f) ? g_reg_sum[tid] / (denom * denom) : 0.f;
            g_cls_sum[tid] = 0.f;
            g_reg_sum[tid] = 0.f;
            g_npos[tid]    = 0.f;
        }
        #pragma unroll
        for (int off = 16; off > 0; off >>= 1) {
            cl += __shfl_down_sync(full, cl, off);
            rg += __shfl_down_sync(full, rg, off);
        }
        if (tid == 0) {
            out[0] = cl / (float)B;
            out[1] = rg / (float)B;
            g_done = 0u;
        }
    }
}

extern "C" void kernel_launch(void* const* d_in, const int* in_sizes, int n_in,
                              void* d_out, int out_size) {
    const float* pred    = (const float*)d_in[0];  // (B, A, 5+C) f32
    const float* ann     = (const float*)d_in[1];  // (B, M, 5) f32
    const float* anchors = (const float*)d_in[2];  // (A, 4) f32
    float* out = (float*)d_out;

    const int A = in_sizes[2] / 4;
    const int B = in_sizes[0] / (A * (NUM_CLASSES + 5));
    const int M = in_sizes[1] / (B * 5);

    dim3 grid((A + TPB - 1) / TPB, B);
    yolo_loss_fused<<<grid, TPB>>>(pred, ann, anchors, out, A, M, B);
}

// round 11
// speedup vs baseline: 1.1951x; 1.1951x over previous
#include <cuda_runtime.h>
#include <cuda_bf16.h>

// YOLOv3 loss, sm_103a — R7: cell-centric (3 anchors/thread).
// All 3 anchor types at a grid cell share their center (anchors are type-major),
// so per (cell, box) the corner min/max work is computed ONCE via
//   ow_t = min(hw_t, bx2-cx) + min(hw_t, cx-bx1)   (and same for y),
// then screened exactly with 3*inter >= areaA_t + area_m (division-free).
// Rare hits (~0.3%) take a __noinline__ cold path: exact argmax + losses.

#define NUM_CLASSES 80
#define NA 3
#define MAXB 64
#define MAXM 64
#define TPB 256

__device__ float        g_cls_sum[MAXB];   // zero-initialized at module load
__device__ float        g_reg_sum[MAXB];
__device__ float        g_npos[MAXB];
__device__ unsigned int g_done;

__device__ __forceinline__ float sigmoidf_fast(float x) {
    return 1.0f / (1.0f + __expf(-x));
}

// Cold path: exact argmax over boxes + exact positivity + loss accumulation.
__device__ __noinline__ void anchor_loss(
    float cx, float cy, float aw, float ah,
    const float4* s_corners, const float* s_am,
    const float* s_cx, const float* s_cy,
    const float* s_w, const float* s_h, const float* s_cl,
    int cnt, const float* __restrict__ row,
    float& clsc, float& regc, float& posc)
{
    const float hw = 0.5f * aw, hh = 0.5f * ah;
    const float ax1 = cx - hw, ay1 = cy - hh;
    const float ax2 = cx + hw, ay2 = cy + hh;
    const float areaA = aw * ah;

    // (inter, union) argmax; a/b > c/d ⟺ a·d > c·b (unions > 0).
    // Init (-1,1): first box wins; strict '>' keeps first max -> jnp.argmax.
    float bI = -1.f, bU = 1.f;
    int   bi = 0;
    for (int m = 0; m < cnt; m++) {
        float4 c = s_corners[m];
        float iw = fmaxf(fminf(ax2, c.z) - fmaxf(ax1, c.x), 0.f);
        float ih = fmaxf(fminf(ay2, c.w) - fmaxf(ay1, c.y), 0.f);
        float inter = iw * ih;
        float uni   = areaA + s_am[m] - inter;
        if (inter * bU > bI * uni) { bI = inter; bU = uni; bi = m; }
    }
    // exact positivity recheck (screen is a superset): IoU>=0.5 ⟺ 2·bI >= bU
    if (2.0f * bI < bU) return;

    posc += 1.f;

    // regression: sum of squared errors (both /denom deferred to finalize)
    float r0 = row[0], r1 = row[1], r2 = row[2], r3 = row[3], r4 = row[4];
    float stx = sigmoidf_fast(s_cx[bi] - cx);
    float sty = sigmoidf_fast(s_cy[bi] - cy);
    float tw  = __logf(fmaxf(s_w[bi], 1.f) / aw);
    float th  = __logf(fmaxf(s_h[bi], 1.f) / ah);
    float d0 = sigmoidf_fast(r0) - stx;
    float d1 = sigmoidf_fast(r1) - sty;
    float d2 = r2 - tw;
    float d3 = r3 - th;
    float d4 = r4 - 1.0f;
    regc += d0*d0 + d1*d1 + d2*d2 + d3*d3 + d4*d4;

    // one-hot BCE collapsed: -( log p_t - log(1-p_t) + sum_c log(1-p_c) )
    float acc = 0.f;
    #pragma unroll 8
    for (int c = 0; c < NUM_CLASSES; c++)
        acc += __logf(1.0f - row[5 + c]);
    int t = (int)s_cl[bi];
    float pt = row[5 + t];
    clsc += -(__logf(pt) - __logf(1.0f - pt) + acc);
}

__global__ void __launch_bounds__(TPB)
yolo_loss_fused(const float* __restrict__ pred,
                const float* __restrict__ ann,
                const float* __restrict__ anchors,
                float* __restrict__ out,
                int A, int G2, int M, int B) {
    __shared__ float4 s_corners[MAXM];               // x1,y1,x2,y2 (valid, compacted)
    __shared__ float  s_am[MAXM];
    __shared__ float  s_cx[MAXM], s_cy[MAXM], s_w[MAXM], s_h[MAXM], s_cl[MAXM];
    __shared__ int    s_cnt;
    __shared__ int    s_last;

    const int b   = blockIdx.y;
    const int tid = threadIdx.x;

    // ---- warp 0: load + compact valid boxes (M <= 32), order-preserving ----
    if (tid < 32) {
        bool  valid = false;
        float x = 0.f, y = 0.f, w = 0.f, h = 0.f, cl = -1.f;
        if (tid < M) {
            const float* bm = ann + ((size_t)b * M + tid) * 5;
            x = bm[0]; y = bm[1]; w = bm[2]; h = bm[3]; cl = bm[4];
            valid = (cl != -1.0f);
        }
        unsigned mask = __ballot_sync(0xffffffffu, valid);
        if (valid) {
            int slot = __popc(mask & ((1u << tid) - 1u));
            s_corners[slot] = make_float4(x, y, x + w, y + h);
            s_am[slot] = w * h;
            s_cx[slot] = x + 0.5f * w;
            s_cy[slot] = y + 0.5f * h;
            s_w[slot]  = w;
            s_h[slot]  = h;
            s_cl[slot] = cl;
        }
        if (tid == 0) s_cnt = __popc(mask);
    }
    __syncthreads();

    const int cnt  = s_cnt;
    const int cell = blockIdx.x * TPB + tid;
    float clsc = 0.f, regc = 0.f, posc = 0.f;

    if (cell < G2) {
        // 3 anchor types at this cell (type-major layout, shared center)
        const float4 a0 = __ldg((const float4*)anchors + cell);
        const float4 a1 = __ldg((const float4*)anchors + G2 + cell);
        const float4 a2 = __ldg((const float4*)anchors + 2 * G2 + cell);
        const float cx = a0.x, cy = a0.y;
        const float hw0 = 0.5f * a0.z, hh0 = 0.5f * a0.w, A0 = a0.z * a0.w;
        const float hw1 = 0.5f * a1.z, hh1 = 0.5f * a1.w, A1 = a1.z * a1.w;
        const float hw2 = 0.5f * a2.z, hh2 = 0.5f * a2.w, A2 = a2.z * a2.w;

        // ---- HOT screening: per box, shared offsets + per-type overlap.
        // ow = min(hw,u)+min(hw,v) equals the corner-form overlap width.
        // max(ow,0)*oh: no false negatives; no far-box (both-negative) false
        // positives. IoU>=0.5 ⟺ 3·inter >= areaA+am (exact, division-free).
        bool h0 = false, h1 = false, h2 = false;
        #pragma unroll 4
        for (int m = 0; m < cnt; m++) {
            const float4 c  = s_corners[m];
            const float  am = s_am[m];
            const float  u = c.z - cx, v = cx - c.x;
            const float  p = c.w - cy, q = cy - c.y;

            float ow0 = fminf(hw0, u) + fminf(hw0, v);
            float oh0 = fminf(hh0, p) + fminf(hh0, q);
            h0 |= (3.0f * (fmaxf(ow0, 0.f) * oh0) >= A0 + am);

            float ow1 = fminf(hw1, u) + fminf(hw1, v);
            float oh1 = fminf(hh1, p) + fminf(hh1, q);
            h1 |= (3.0f * (fmaxf(ow1, 0.f) * oh1) >= A1 + am);

            float ow2 = fminf(hw2, u) + fminf(hw2, v);
            float oh2 = fminf(hh2, p) + fminf(hh2, q);
            h2 |= (3.0f * (fmaxf(ow2, 0.f) * oh2) >= A2 + am);
        }

        if (h0 | h1 | h2) {
            const size_t rowbase = (size_t)b * A;
            if (h0) anchor_loss(cx, cy, a0.z, a0.w, s_corners, s_am,
                                s_cx, s_cy, s_w, s_h, s_cl, cnt,
                                pred + (rowbase + cell) * (NUM_CLASSES + 5),
                                clsc, regc, posc);
            if (h1) anchor_loss(cx, cy, a1.z, a1.w, s_corners, s_am,
                                s_cx, s_cy, s_w, s_h, s_cl, cnt,
                                pred + (rowbase + G2 + cell) * (NUM_CLASSES + 5),
                                clsc, regc, posc);
            if (h2) anchor_loss(cx, cy, a2.z, a2.w, s_corners, s_am,
                                s_cx, s_cy, s_w, s_h, s_cl, cnt,
                                pred + (rowbase + 2 * G2 + cell) * (NUM_CLASSES + 5),
                                clsc, regc, posc);
        }
    }

    // warp reduce, one conditional atomic triple per warp
    const unsigned full = 0xffffffffu;
    #pragma unroll
    for (int off = 16; off > 0; off >>= 1) {
        clsc += __shfl_down_sync(full, clsc, off);
        regc += __shfl_down_sync(full, regc, off);
        posc += __shfl_down_sync(full, posc, off);
    }
    if ((tid & 31) == 0 && posc > 0.f) {
        atomicAdd(&g_cls_sum[b], clsc);
        atomicAdd(&g_reg_sum[b], regc);
        atomicAdd(&g_npos[b],    posc);
    }

    // ---- last-block finalize ----
    __syncthreads();
    if (tid == 0) {
        __threadfence();
        unsigned total = gridDim.x * gridDim.y;
        unsigned old = atomicAdd(&g_done, 1u);
        s_last = (old == total - 1u);
    }
    __syncthreads();

    if (s_last && tid < 32) {
        __threadfence();
        float cl = 0.f, rg = 0.f;
        if (tid < B) {
            float n = g_npos[tid];
            float denom = fmaxf(n, 1.f);
            cl = g_cls_sum[tid] / denom;
            rg = (n > 0.f) ? g_reg_sum[tid] / (denom * denom) : 0.f;
            g_cls_sum[tid] = 0.f;
            g_reg_sum[tid] = 0.f;
            g_npos[tid]    = 0.f;
        }
        #pragma unroll
        for (int off = 16; off > 0; off >>= 1) {
            cl += __shfl_down_sync(full, cl, off);
            rg += __shfl_down_sync(full, rg, off);
        }
        if (tid == 0) {
            out[0] = cl / (float)B;
            out[1] = rg / (float)B;
            g_done = 0u;
        }
    }
}

extern "C" void kernel_launch(void* const* d_in, const int* in_sizes, int n_in,
                              void* d_out, int out_size) {
    const float* pred    = (const float*)d_in[0];  // (B, A, 5+C) f32
    const float* ann     = (const float*)d_in[1];  // (B, M, 5) f32
    const float* anchors = (const float*)d_in[2];  // (NA, G, G, 4) f32, type-major
    float* out = (float*)d_out;

    const int A  = in_sizes[2] / 4;
    const int G2 = A / NA;                         // cells per image
    const int B  = in_sizes[0] / (A * (NUM_CLASSES + 5));
    const int M  = in_sizes[1] / (B * 5);

    dim3 grid((G2 + TPB - 1) / TPB, B);
    yolo_loss_fused<<<grid, TPB>>>(pred, ann, anchors, out, A, G2, M, B);
}